// round 11
// baseline (speedup 1.0000x reference)
#include <cuda_runtime.h>

// Problem constants
#define NH    5
#define LD    10
#define PROJ  50           // NH*LD
#define C_DIM 256
#define B_DIM 32
#define HW    4096
#define M_ROWS (B_DIM * C_DIM)   // 8192
#define BN_EPS 1e-5f
#define KSPLIT 8
#define KSLICE (HW / KSPLIT)     // 512

// Scratch (device globals: no allocations allowed)
__device__ float g_Pp[3][KSPLIT][M_ROWS * PROJ];  // split-K partials
__device__ float g_P[3][M_ROWS * PROJ];           // reduced projections
__device__ float g_Va[M_ROWS * PROJ];             // attention output
__device__ float g_osum[64][M_ROWS];              // per-(nblk,row) sum of out
__device__ float g_osq[64][M_ROWS];               // per-(nblk,row) sum of out^2
__device__ float g_scale[C_DIM];
__device__ float g_shift[C_DIM];

__device__ __forceinline__ unsigned f2tf32(float x) {
    unsigned y;
    asm("cvt.rna.tf32.f32 %0, %1;" : "=r"(y) : "f"(x));
    return y;
}

__device__ __forceinline__ void mma_tf32(float c[4], unsigned a0, unsigned a1,
                                         unsigned a2, unsigned a3,
                                         unsigned b0, unsigned b1) {
    asm volatile(
        "mma.sync.aligned.m16n8k8.row.col.f32.tf32.tf32.f32 "
        "{%0,%1,%2,%3}, {%4,%5,%6,%7}, {%8,%9}, {%0,%1,%2,%3};\n"
        : "+f"(c[0]), "+f"(c[1]), "+f"(c[2]), "+f"(c[3])
        : "r"(a0), "r"(a1), "r"(a2), "r"(a3), "r"(b0), "r"(b1));
}

__device__ __forceinline__ void cp_async16(unsigned smem_dst, const void* gsrc) {
    asm volatile("cp.async.cg.shared.global [%0], [%1], 16;\n"
                 :: "r"(smem_dst), "l"(gsrc));
}
__device__ __forceinline__ void cp_commit() {
    asm volatile("cp.async.commit_group;\n");
}
__device__ __forceinline__ void cp_wait0() {
    asm volatile("cp.async.wait_group 0;\n");
}

// ---------------------------------------------------------------------------
// K1: projection GEMMs, TF32 TC, split-K x8, cp.async A double-buffer,
// W operand stored PRE-PACKED in mma-fragment order:
//   Wp[buf][N16 0..3][K8 0..3][lane 0..31][4 slots]
//   lane = g*4+t;  slots = {W[N16*16+g][K8*8+t], W[..+8+g][t],
//                           W[g][t+4], W[..+8+g][t+4]}
//   -> one LDS128 per (mi,ks) fragment.
// As[2][128][32] raw fp32 bits, XOR swizzle (k ^ 4*(row&7)), scalar B-LDS.
// Dynamic smem: 32768 (As) + 16384 (Wp) = 49152 B.
// SWAPPED mma roles: mma-A = W (n50 as M), mma-B = data rows (as N).
// ---------------------------------------------------------------------------
#define AS_ELT(buf, row, col) smd[((buf) * 128 + (row)) * 32 + (col)]
#define PROJ_SMEM_BYTES 49152

__global__ __launch_bounds__(256) void k_proj_tc(
    const float* __restrict__ q, const float* __restrict__ k,
    const float* __restrict__ v,
    const float* __restrict__ wq, const float* __restrict__ wk,
    const float* __restrict__ wv)
{
    extern __shared__ unsigned smd[];
    unsigned* Wpf = smd + 8192;                 // 2 * 2048 u32
    const uint4* Wp4 = (const uint4*)(smd + 8192);

    const int z = blockIdx.z;
    const float* __restrict__ A = (z == 0) ? q : (z == 1) ? k : v;
    const float* __restrict__ W = (z == 0) ? wq : (z == 1) ? wk : wv;
    const int slice = blockIdx.y;
    float* __restrict__ P = g_Pp[z][slice];
    const int kbase = slice * KSLICE;

    const int tid  = threadIdx.x;
    const int warp = tid >> 5;
    const int lane = tid & 31;
    const int g = lane >> 2;
    const int t = lane & 3;
    const int wrow = (warp & 3) * 32;   // data-row group (mma-N)
    const int m0 = blockIdx.x * 128;

    const unsigned as_base = (unsigned)__cvta_generic_to_shared(&smd[0]);

    // zero both W buffers (pad slots for n>=50 stay zero forever)
    for (int i = tid; i < 2 * 2048; i += 256) Wpf[i] = 0u;
    __syncthreads();

    float acc[2][4][4];
#pragma unroll
    for (int mi = 0; mi < 2; mi++)
#pragma unroll
        for (int ni = 0; ni < 4; ni++)
#pragma unroll
            for (int r = 0; r < 4; r++) acc[mi][ni][r] = 0.f;

    // W loader mapping: thread -> n = tid&63, k base = (tid>>6)*8 (+j, j<8)
    const int wl_n  = tid & 63;
    const int wl_k0 = (tid >> 6) * 8;
    const int wl_N16 = wl_n >> 4;
    const int wl_hi  = (wl_n >> 3) & 1;
    const int wl_g   = wl_n & 7;
    const int wl_K8  = wl_k0 >> 3;        // constant per thread

    auto issue_A = [&](int buf, int k0) {
#pragma unroll
        for (int j = 0; j < 4; j++) {
            int i   = tid + j * 256;
            int row = i >> 3;
            int c4  = (i & 7) * 4;
            int sc  = c4 ^ (4 * (row & 7));
            unsigned dst = as_base + (((buf * 128 + row) * 32 + sc) << 2);
            cp_async16(dst, &A[(size_t)(m0 + row) * HW + k0 + c4]);
        }
        cp_commit();
    };
    auto load_W = [&](int buf, int k0) {
        if (wl_n < PROJ) {
            int base = buf * 2048 + ((wl_N16 * 4 + wl_K8) * 32) * 4;
#pragma unroll
            for (int j = 0; j < 8; j++) {
                int tt   = j & 3;
                int slot = wl_hi + 2 * (j >> 2);
                Wpf[base + (wl_g * 4 + tt) * 4 + slot] =
                    f2tf32(W[(k0 + wl_k0 + j) * PROJ + wl_n]);
            }
        }
    };

    // prologue
    issue_A(0, kbase);
    load_W(0, kbase);
    cp_wait0();
    __syncthreads();

    const int NT = KSLICE / 32;   // 16 tiles
    for (int kt = 0; kt < NT; kt++) {
        const int buf = kt & 1;
        const bool haveNext = (kt + 1 < NT);
        if (haveNext) {
            const int k0n = kbase + (kt + 1) * 32;
            issue_A(buf ^ 1, k0n);
            load_W(buf ^ 1, k0n);   // idle buffer, no race
        }

#pragma unroll
        for (int ks = 0; ks < 4; ks++) {
            const int kb = ks * 8;
            uint4 av[2];
#pragma unroll
            for (int mi = 0; mi < 2; mi++) {
                int N16 = (warp >> 2) * 2 + mi;
                av[mi] = Wp4[buf * 512 + (N16 * 4 + ks) * 32 + lane];
            }
#pragma unroll
            for (int ni = 0; ni < 4; ni++) {
                int row = wrow + ni * 8 + g;
                unsigned b0 = AS_ELT(buf, row, (kb + t) ^ (4 * (row & 7)));
                unsigned b1 = AS_ELT(buf, row, (kb + t + 4) ^ (4 * (row & 7)));
                mma_tf32(acc[0][ni], av[0].x, av[0].y, av[0].z, av[0].w, b0, b1);
                mma_tf32(acc[1][ni], av[1].x, av[1].y, av[1].z, av[1].w, b0, b1);
            }
        }

        if (haveNext) {
            cp_wait0();
            __syncthreads();
        }
    }

    // Epilogue: c0=D[g][2t] -> P[row=wrow+ni*8+2t][n50=wcol+mi*16+g]
    const int wcol = (warp >> 2) * 32;
#pragma unroll
    for (int mi = 0; mi < 2; mi++) {
#pragma unroll
        for (int ni = 0; ni < 4; ni++) {
            int col0 = wcol + mi * 16 + g;
            int col2 = col0 + 8;
            int prow = m0 + wrow + ni * 8 + 2 * t;
            if (col0 < PROJ) {
                P[prow * PROJ + col0]       = acc[mi][ni][0];
                P[(prow + 1) * PROJ + col0] = acc[mi][ni][1];
            }
            if (col2 < PROJ) {
                P[prow * PROJ + col2]       = acc[mi][ni][2];
                P[(prow + 1) * PROJ + col2] = acc[mi][ni][3];
            }
        }
    }
}

// ---------------------------------------------------------------------------
// K1b: reduce split-K partials.
// ---------------------------------------------------------------------------
__global__ __launch_bounds__(256) void k_reduceP()
{
    const int i = blockIdx.x * 256 + threadIdx.x;
    const int per_z = (M_ROWS * PROJ) / 4;
    const int z = i / per_z;
    const int r = i - z * per_z;
    const float4* __restrict__ p = (const float4*)g_Pp;
    float4 o = make_float4(0.f, 0.f, 0.f, 0.f);
#pragma unroll
    for (int j = 0; j < KSPLIT; j++) {
        float4 a = p[(size_t)(z * KSPLIT + j) * per_z + r];
        o.x += a.x; o.y += a.y; o.z += a.z; o.w += a.w;
    }
    ((float4*)g_P)[i] = o;
}

// ---------------------------------------------------------------------------
// K2: attention (tiny). One block per batch, one thread per channel.
// ---------------------------------------------------------------------------
__global__ __launch_bounds__(256) void k_attn()
{
    const int b = blockIdx.x;
    const int c = threadIdx.x;
    const int lane = c & 31;
    const int wid  = c >> 5;

    const float* __restrict__ pq = &g_P[0][(b * C_DIM + c) * PROJ];
    const float* __restrict__ pk = &g_P[1][(b * C_DIM + c) * PROJ];
    const float* __restrict__ pv = &g_P[2][(b * C_DIM + c) * PROJ];

    float s[NH * NH];
#pragma unroll
    for (int i = 0; i < NH; i++)
#pragma unroll
        for (int j = 0; j < NH; j++) {
            float a = 0.f;
#pragma unroll
            for (int l = 0; l < LD; l++)
                a = fmaf(pq[i * LD + l], pk[j * LD + l], a);
            s[i * NH + j] = a;
        }

    __shared__ float sW[8][NH * NH];
    __shared__ float sA[NH * NH];

#pragma unroll
    for (int tt = 0; tt < NH * NH; tt++) {
        float x = s[tt];
#pragma unroll
        for (int off = 16; off > 0; off >>= 1)
            x += __shfl_down_sync(0xffffffffu, x, off);
        if (lane == 0) sW[wid][tt] = x;
    }
    __syncthreads();

    if (c < NH) {
        const int i = c;
        const float inv_scale = rsqrtf((float)(C_DIM * LD));
        float row[NH];
        float mx = -1e30f;
#pragma unroll
        for (int j = 0; j < NH; j++) {
            float a = 0.f;
#pragma unroll
            for (int w = 0; w < 8; w++) a += sW[w][i * NH + j];
            row[j] = a * inv_scale;
            mx = fmaxf(mx, row[j]);
        }
        float sum = 0.f;
#pragma unroll
        for (int j = 0; j < NH; j++) { row[j] = expf(row[j] - mx); sum += row[j]; }
        float inv = 1.f / sum;
#pragma unroll
        for (int j = 0; j < NH; j++) sA[i * NH + j] = row[j] * inv;
    }
    __syncthreads();

    float* __restrict__ va = &g_Va[(b * C_DIM + c) * PROJ];
#pragma unroll
    for (int n = 0; n < NH; n++)
#pragma unroll
        for (int l = 0; l < LD; l++) {
            float a = pv[n * LD + l];
#pragma unroll
            for (int j = 0; j < NH; j++)
                a = fmaf(sA[n * NH + j], pv[j * LD + l], a);
            va[n * LD + l] = a;
        }
}

// ---------------------------------------------------------------------------
// Shared machinery for the output GEMM (K padded 50->56, 7 k-steps).
// Pre-packed fragment layouts in a 43008-B pool:
//   Wp[N16 0..3][K8 0..6][lane][4]  (wfc tile, mma-A)  -> 3584 u32
//   Vp[R8 0..15][K8 0..6][lane][2]  (Va tile, mma-B)   -> 7168 u32
// After the mainloop the pool is overlaid by Acc[128][68] for the
// streamed float4 epilogue.
// ---------------------------------------------------------------------------
#define OUT_FILL_AND_MMA(POOL, ACC)                                            \
    unsigned* Wpf = POOL;                                                      \
    unsigned* Vpf = POOL + 3584;                                               \
    const uint4* Wp4 = (const uint4*)POOL;                                     \
    const uint2* Vp2 = (const uint2*)(POOL + 3584);                            \
    for (int i = tid; i < 64 * 56; i += 256) {                                 \
        int n  = i & 63;                                                       \
        int kk = i >> 6;                                                       \
        float val = (kk < PROJ) ? wfc[kk * HW + n0 + n] : 0.f;                 \
        int N16 = n >> 4, hi = (n >> 3) & 1, gg = n & 7;                       \
        int K8 = kk >> 3, tt = kk & 3, hf = (kk >> 2) & 1;                     \
        Wpf[((N16 * 7 + K8) * 32 + gg * 4 + tt) * 4 + (hi + 2 * hf)] =         \
            f2tf32(val);                                                       \
    }                                                                          \
    for (int i = tid; i < 128 * 64; i += 256) {                                \
        int kk = i & 63;                                                       \
        if (kk >= 56) continue;                                                \
        int row = i >> 6;                                                      \
        float val = (kk < PROJ) ? g_Va[(m0 + row) * PROJ + kk] : 0.f;          \
        int R8 = row >> 3, gg = row & 7;                                       \
        int K8 = kk >> 3, tt = kk & 3, hf = (kk >> 2) & 1;                     \
        Vpf[((R8 * 7 + K8) * 32 + gg * 4 + tt) * 2 + hf] = f2tf32(val);        \
    }                                                                          \
    __syncthreads();                                                           \
    _Pragma("unroll")                                                          \
    for (int ks = 0; ks < 7; ks++) {                                           \
        uint4 av[2];                                                           \
        _Pragma("unroll")                                                      \
        for (int mi = 0; mi < 2; mi++) {                                       \
            int N16 = (warp >> 2) * 2 + mi;                                    \
            av[mi] = Wp4[(N16 * 7 + ks) * 32 + lane];                          \
        }                                                                      \
        _Pragma("unroll")                                                      \
        for (int ni = 0; ni < 4; ni++) {                                       \
            int R8 = (warp & 3) * 4 + ni;                                      \
            uint2 bv = Vp2[(R8 * 7 + ks) * 32 + lane];                         \
            mma_tf32(ACC[0][ni], av[0].x, av[0].y, av[0].z, av[0].w,           \
                     bv.x, bv.y);                                              \
            mma_tf32(ACC[1][ni], av[1].x, av[1].y, av[1].z, av[1].w,           \
                     bv.x, bv.y);                                              \
        }                                                                      \
    }                                                                          \
    __syncthreads();  /* mainloop reads done; pool may be overlaid */          \
    _Pragma("unroll")                                                          \
    for (int mi = 0; mi < 2; mi++) {                                           \
        _Pragma("unroll")                                                      \
        for (int ni = 0; ni < 4; ni++) {                                       \
            int row = wrow + ni * 8 + 2 * t;                                   \
            int col = wcol + mi * 16 + g;                                      \
            Acc[row][col]         = ACC[mi][ni][0];                            \
            Acc[row + 1][col]     = ACC[mi][ni][1];                            \
            Acc[row][col + 8]     = ACC[mi][ni][2];                            \
            Acc[row + 1][col + 8] = ACC[mi][ni][3];                            \
        }                                                                      \
    }                                                                          \
    __syncthreads();

// ---------------------------------------------------------------------------
// K3a: out stats pass. Computes o = v + Va@wfc for its 128x64 tile and
// reduces per-row sum/sumsq into g_osum/g_osq. Does NOT write out.
// ---------------------------------------------------------------------------
__global__ __launch_bounds__(256) void k_out_stats(
    const float* __restrict__ v, const float* __restrict__ wfc)
{
    __shared__ __align__(16) unsigned pool[3584 + 7168];  // 43008 B
    float (*Acc)[68] = (float(*)[68])pool;

    const int tid  = threadIdx.x;
    const int warp = tid >> 5;
    const int lane = tid & 31;
    const int g = lane >> 2;
    const int t = lane & 3;
    const int wrow = (warp & 3) * 32;
    const int wcol = (warp >> 2) * 32;
    const int n0 = blockIdx.x * 64;
    const int m0 = blockIdx.y * 128;

    float acc[2][4][4];
#pragma unroll
    for (int mi = 0; mi < 2; mi++)
#pragma unroll
        for (int ni = 0; ni < 4; ni++)
#pragma unroll
            for (int r = 0; r < 4; r++) acc[mi][ni][r] = 0.f;

    OUT_FILL_AND_MMA(pool, acc)

    // streamed stats: 8 x float4 per thread, full row per 16-lane group
#pragma unroll
    for (int it = 0; it < 8; it++) {
        int f   = tid + it * 256;
        int row = f >> 4;
        int c4  = (f & 15) * 4;
        float4 a = *(float4*)&Acc[row][c4];
        size_t gi = (size_t)(m0 + row) * HW + n0 + c4;
        float4 vv = *(const float4*)&v[gi];
        float ox = vv.x + a.x, oy = vv.y + a.y;
        float oz = vv.z + a.z, ow = vv.w + a.w;
        float s  = (ox + oy) + (oz + ow);
        float qq = (ox * ox + oy * oy) + (oz * oz + ow * ow);
#pragma unroll
        for (int msk = 1; msk <= 8; msk <<= 1) {
            s  += __shfl_xor_sync(0xffffffffu, s, msk);
            qq += __shfl_xor_sync(0xffffffffu, qq, msk);
        }
        if ((lane & 15) == 0) {
            g_osum[blockIdx.x][m0 + row] = s;
            g_osq[blockIdx.x][m0 + row]  = qq;
        }
    }
}

// ---------------------------------------------------------------------------
// K4: combine partials -> per-channel scale/shift. 256 blocks x 256 thr.
// ---------------------------------------------------------------------------
__global__ __launch_bounds__(256) void k_bnfinal(
    const float* __restrict__ gamma, const float* __restrict__ beta)
{
    const int c = blockIdx.x;
    const int tid = threadIdx.x;
    float s = 0.f, s2 = 0.f;
    for (int i = tid; i < B_DIM * 64; i += 256) {     // 2048 entries
        int b  = i >> 6;
        int nb = i & 63;
        int row = b * C_DIM + c;
        s  += g_osum[nb][row];
        s2 += g_osq[nb][row];
    }
    __shared__ float rs[256], rs2[256];
    rs[tid] = s; rs2[tid] = s2;
    __syncthreads();
    for (int off = 128; off > 0; off >>= 1) {
        if (tid < off) { rs[tid] += rs[tid + off]; rs2[tid] += rs2[tid + off]; }
        __syncthreads();
    }
    if (tid == 0) {
        const float inv_n = 1.f / (float)(B_DIM * HW);
        float mean = rs[0] * inv_n;
        float var  = rs2[0] * inv_n - mean * mean;
        float sc = gamma[c] * rsqrtf(var + BN_EPS);
        g_scale[c] = sc;
        g_shift[c] = beta[c] - mean * sc;
    }
}

// ---------------------------------------------------------------------------
// K3b: apply pass. RECOMPUTES the same GEMM (bit-identical order), applies
// residual + BN affine, writes out. out = (v + acc)*scale[c] + shift[c].
// ---------------------------------------------------------------------------
__global__ __launch_bounds__(256) void k_apply_gemm(
    const float* __restrict__ v, const float* __restrict__ wfc,
    float* __restrict__ out)
{
    __shared__ __align__(16) unsigned pool[3584 + 7168];  // 43008 B
    float (*Acc)[68] = (float(*)[68])pool;

    const int tid  = threadIdx.x;
    const int warp = tid >> 5;
    const int lane = tid & 31;
    const int g = lane >> 2;
    const int t = lane & 3;
    const int wrow = (warp & 3) * 32;
    const int wcol = (warp >> 2) * 32;
    const int n0 = blockIdx.x * 64;
    const int m0 = blockIdx.y * 128;

    float acc[2][4][4];
#pragma unroll
    for (int mi = 0; mi < 2; mi++)
#pragma unroll
        for (int ni = 0; ni < 4; ni++)
#pragma unroll
            for (int r = 0; r < 4; r++) acc[mi][ni][r] = 0.f;

    OUT_FILL_AND_MMA(pool, acc)

    // streamed epilogue: residual + BN, coalesced float4 stores
#pragma unroll
    for (int it = 0; it < 8; it++) {
        int f   = tid + it * 256;
        int row = f >> 4;
        int c4  = (f & 15) * 4;
        int ch  = (m0 + row) & (C_DIM - 1);
        float sc = g_scale[ch], sh = g_shift[ch];
        float4 a = *(float4*)&Acc[row][c4];
        size_t gi = (size_t)(m0 + row) * HW + n0 + c4;
        float4 vv = *(const float4*)&v[gi];
        float4 o;
        o.x = fmaf(vv.x + a.x, sc, sh);
        o.y = fmaf(vv.y + a.y, sc, sh);
        o.z = fmaf(vv.z + a.z, sc, sh);
        o.w = fmaf(vv.w + a.w, sc, sh);
        *(float4*)&out[gi] = o;
    }
}

// ---------------------------------------------------------------------------
extern "C" void kernel_launch(void* const* d_in, const int* in_sizes, int n_in,
                              void* d_out, int out_size)
{
    (void)in_sizes; (void)n_in; (void)out_size;
    const float* q     = (const float*)d_in[0];
    const float* k     = (const float*)d_in[1];
    const float* v     = (const float*)d_in[2];
    const float* wq    = (const float*)d_in[3];
    const float* wk    = (const float*)d_in[4];
    const float* wv    = (const float*)d_in[5];
    const float* wfc   = (const float*)d_in[6];
    const float* gamma = (const float*)d_in[7];
    const float* beta  = (const float*)d_in[8];
    float* out = (float*)d_out;

    cudaFuncSetAttribute(k_proj_tc,
                         cudaFuncAttributeMaxDynamicSharedMemorySize,
                         PROJ_SMEM_BYTES);

    k_proj_tc<<<dim3(M_ROWS / 128, KSPLIT, 3), 256, PROJ_SMEM_BYTES>>>(
        q, k, v, wq, wk, wv);
    k_reduceP<<<(3 * M_ROWS * PROJ / 4) / 256, 256>>>();
    k_attn<<<B_DIM, 256>>>();
    k_out_stats<<<dim3(HW / 64, M_ROWS / 128), 256>>>(v, wfc);
    k_bnfinal<<<C_DIM, 256>>>(gamma, beta);
    k_apply_gemm<<<dim3(HW / 64, M_ROWS / 128), 256>>>(v, wfc, out);
}

// round 12
// speedup vs baseline: 1.8265x; 1.8265x over previous
#include <cuda_runtime.h>

// Problem constants
#define NH    5
#define LD    10
#define PROJ  50           // NH*LD
#define C_DIM 256
#define B_DIM 32
#define HW    4096
#define M_ROWS (B_DIM * C_DIM)   // 8192
#define BN_EPS 1e-5f
#define KSPLIT 4
#define KSLICE (HW / KSPLIT)     // 1024

// Scratch (device globals: no allocations allowed)
__device__ float g_Pp[3][KSPLIT][M_ROWS * PROJ];  // split-K partials
__device__ float g_P[3][M_ROWS * PROJ];           // reduced projections
// Packed mma fragments (built once per launch, L2-resident):
//   g_Wp: wfc as mma-A frags  [nblk 0..63][N16 0..3][K8 0..6][lane][uint4]
//   g_Vp: Va  as mma-B frags  [R8 0..1023][K8 0..6][lane][uint2]
__device__ uint4 g_Wp[64 * 4 * 7 * 32];           // 917504 B
__device__ uint2 g_Vp[1024 * 7 * 32];             // 1835008 B
__device__ float g_osum[64][M_ROWS];              // per-(nblk,row) sum of out
__device__ float g_osq[64][M_ROWS];               // per-(nblk,row) sum of out^2
__device__ float g_scale[C_DIM];
__device__ float g_shift[C_DIM];

__device__ __forceinline__ unsigned f2tf32(float x) {
    unsigned y;
    asm("cvt.rna.tf32.f32 %0, %1;" : "=r"(y) : "f"(x));
    return y;
}

__device__ __forceinline__ void mma_tf32(float c[4], unsigned a0, unsigned a1,
                                         unsigned a2, unsigned a3,
                                         unsigned b0, unsigned b1) {
    asm volatile(
        "mma.sync.aligned.m16n8k8.row.col.f32.tf32.tf32.f32 "
        "{%0,%1,%2,%3}, {%4,%5,%6,%7}, {%8,%9}, {%0,%1,%2,%3};\n"
        : "+f"(c[0]), "+f"(c[1]), "+f"(c[2]), "+f"(c[3])
        : "r"(a0), "r"(a1), "r"(a2), "r"(a3), "r"(b0), "r"(b1));
}

__device__ __forceinline__ void cp_async16(unsigned smem_dst, const void* gsrc) {
    asm volatile("cp.async.cg.shared.global [%0], [%1], 16;\n"
                 :: "r"(smem_dst), "l"(gsrc));
}
__device__ __forceinline__ void cp_commit() {
    asm volatile("cp.async.commit_group;\n");
}
__device__ __forceinline__ void cp_wait0() {
    asm volatile("cp.async.wait_group 0;\n");
}

// ---------------------------------------------------------------------------
// K1: projection GEMMs (R7 version: static smem, W single-buffer + reg
// prefetch, cp.async A double-buffer, split-K x4).
// SWAPPED mma roles: mma-A = W (n50 as M), mma-B = data rows (as N).
// A smem: [2][128][32] raw fp32 bits, XOR swizzle (k ^ 4*(row&7)).
// W smem: [64][36] tf32 (rows>=50 zero).
// ---------------------------------------------------------------------------
__global__ __launch_bounds__(256) void k_proj_tc(
    const float* __restrict__ q, const float* __restrict__ k,
    const float* __restrict__ v,
    const float* __restrict__ wq, const float* __restrict__ wk,
    const float* __restrict__ wv)
{
    const int z = blockIdx.z;
    const float* __restrict__ A = (z == 0) ? q : (z == 1) ? k : v;
    const float* __restrict__ W = (z == 0) ? wq : (z == 1) ? wk : wv;
    const int slice = blockIdx.y;
    float* __restrict__ P = g_Pp[z][slice];
    const int kbase = slice * KSLICE;

    __shared__ unsigned As[2][128][32];
    __shared__ unsigned Wsm[64][36];

    const int tid  = threadIdx.x;
    const int warp = tid >> 5;
    const int lane = tid & 31;
    const int g = lane >> 2;
    const int t = lane & 3;
    const int wrow = (warp & 3) * 32;   // data-row group (mma-N)
    const int wcol = (warp >> 2) * 32;  // n50 group (mma-M)
    const int m0 = blockIdx.x * 128;

    const unsigned as_base = (unsigned)__cvta_generic_to_shared(&As[0][0][0]);

    // zero W buffer once (rows >= 50 stay zero forever)
    for (int i = tid; i < 64 * 36; i += 256) (&Wsm[0][0])[i] = 0u;
    __syncthreads();

    float acc[2][4][4];
#pragma unroll
    for (int mi = 0; mi < 2; mi++)
#pragma unroll
        for (int ni = 0; ni < 4; ni++)
#pragma unroll
            for (int r = 0; r < 4; r++) acc[mi][ni][r] = 0.f;

    const int wl_n  = tid & 63;       // W load: n index
    const int wl_k0 = (tid >> 6) * 8; // W load: k base (0,8,16,24)

    auto issue_A = [&](int buf, int k0) {
#pragma unroll
        for (int j = 0; j < 4; j++) {
            int i   = tid + j * 256;
            int row = i >> 3;
            int c4  = (i & 7) * 4;
            int sc  = c4 ^ (4 * (row & 7));
            unsigned dst = as_base + ((buf * 128 + row) * 32 + sc) * 4;
            cp_async16(dst, &A[(size_t)(m0 + row) * HW + k0 + c4]);
        }
        cp_commit();
    };

    // prologue: tile 0
    issue_A(0, kbase);
    if (wl_n < PROJ) {
#pragma unroll
        for (int j = 0; j < 8; j++)
            Wsm[wl_n][wl_k0 + j] = f2tf32(W[(kbase + wl_k0 + j) * PROJ + wl_n]);
    }
    cp_wait0();
    __syncthreads();

    const int NT = KSLICE / 32;   // 32 tiles
    for (int kt = 0; kt < NT; kt++) {
        const int buf = kt & 1;
        const bool haveNext = (kt + 1 < NT);
        float wreg[8];
        if (haveNext) {
            const int k0n = kbase + (kt + 1) * 32;
            issue_A(buf ^ 1, k0n);
            if (wl_n < PROJ) {
#pragma unroll
                for (int j = 0; j < 8; j++)
                    wreg[j] = W[(k0n + wl_k0 + j) * PROJ + wl_n];
            }
        }

#pragma unroll
        for (int ks = 0; ks < 4; ks++) {
            const int kb = ks * 8;
            unsigned a[2][4];
#pragma unroll
            for (int mi = 0; mi < 2; mi++) {
                int n = wcol + mi * 16 + g;
                a[mi][0] = Wsm[n][kb + t];
                a[mi][1] = Wsm[n + 8][kb + t];
                a[mi][2] = Wsm[n][kb + t + 4];
                a[mi][3] = Wsm[n + 8][kb + t + 4];
            }
#pragma unroll
            for (int ni = 0; ni < 4; ni++) {
                int row = wrow + ni * 8 + g;
                unsigned b0 = As[buf][row][(kb + t) ^ (4 * (row & 7))];
                unsigned b1 = As[buf][row][(kb + t + 4) ^ (4 * (row & 7))];
                mma_tf32(acc[0][ni], a[0][0], a[0][1], a[0][2], a[0][3], b0, b1);
                mma_tf32(acc[1][ni], a[1][0], a[1][1], a[1][2], a[1][3], b0, b1);
            }
        }

        if (haveNext) {
            cp_wait0();
            __syncthreads();
            if (wl_n < PROJ) {
#pragma unroll
                for (int j = 0; j < 8; j++)
                    Wsm[wl_n][wl_k0 + j] = f2tf32(wreg[j]);
            }
            __syncthreads();
        }
    }

    // Epilogue: c0=D[g][2t] -> P[row=wrow+ni*8+2t][n50=wcol+mi*16+g]
#pragma unroll
    for (int mi = 0; mi < 2; mi++) {
#pragma unroll
        for (int ni = 0; ni < 4; ni++) {
            int col0 = wcol + mi * 16 + g;
            int col2 = col0 + 8;
            int prow = m0 + wrow + ni * 8 + 2 * t;
            if (col0 < PROJ) {
                P[prow * PROJ + col0]       = acc[mi][ni][0];
                P[(prow + 1) * PROJ + col0] = acc[mi][ni][1];
            }
            if (col2 < PROJ) {
                P[prow * PROJ + col2]       = acc[mi][ni][2];
                P[(prow + 1) * PROJ + col2] = acc[mi][ni][3];
            }
        }
    }
}

// ---------------------------------------------------------------------------
// K1b: reduce split-K partials.
// ---------------------------------------------------------------------------
__global__ __launch_bounds__(256) void k_reduceP()
{
    const int i = blockIdx.x * 256 + threadIdx.x;
    const int per_z = (M_ROWS * PROJ) / 4;
    const int z = i / per_z;
    const int r = i - z * per_z;
    const float4* __restrict__ p = (const float4*)g_Pp;
    float4 a = p[(size_t)(z * KSPLIT + 0) * per_z + r];
    float4 b = p[(size_t)(z * KSPLIT + 1) * per_z + r];
    float4 c = p[(size_t)(z * KSPLIT + 2) * per_z + r];
    float4 d = p[(size_t)(z * KSPLIT + 3) * per_z + r];
    float4 o;
    o.x = (a.x + b.x) + (c.x + d.x);
    o.y = (a.y + b.y) + (c.y + d.y);
    o.z = (a.z + b.z) + (c.z + d.z);
    o.w = (a.w + b.w) + (c.w + d.w);
    ((float4*)g_P)[i] = o;
}

// ---------------------------------------------------------------------------
// K1c: pack wfc into mma-A fragment order (once; 917 KB, L2-resident).
// idx -> kk = idx>>12 (0..55), n = idx&4095 (coalesced wfc loads).
// ---------------------------------------------------------------------------
__global__ __launch_bounds__(256) void k_packW(const float* __restrict__ wfc)
{
    const int idx = blockIdx.x * 256 + threadIdx.x;   // 0 .. 229375
    const int kk = idx >> 12;
    const int n  = idx & 4095;
    float val = (kk < PROJ) ? wfc[kk * HW + n] : 0.f;
    const int nblk = n >> 6, n6 = n & 63;
    const int N16 = n6 >> 4, hi = (n6 >> 3) & 1, gg = n6 & 7;
    const int K8 = kk >> 3, tt = kk & 3, hf = (kk >> 2) & 1;
    ((unsigned*)g_Wp)[(((nblk * 4 + N16) * 7 + K8) * 32 + gg * 4 + tt) * 4
                      + hi + 2 * hf] = f2tf32(val);
}

// ---------------------------------------------------------------------------
// K2: attention (tiny). One block per batch, one thread per channel.
// Writes Va DIRECTLY in packed mma-B fragment order (g_Vp).
// ---------------------------------------------------------------------------
__global__ __launch_bounds__(256) void k_attn()
{
    const int b = blockIdx.x;
    const int c = threadIdx.x;
    const int lane = c & 31;
    const int wid  = c >> 5;

    const float* __restrict__ pq = &g_P[0][(b * C_DIM + c) * PROJ];
    const float* __restrict__ pk = &g_P[1][(b * C_DIM + c) * PROJ];
    const float* __restrict__ pv = &g_P[2][(b * C_DIM + c) * PROJ];

    float s[NH * NH];
#pragma unroll
    for (int i = 0; i < NH; i++)
#pragma unroll
        for (int j = 0; j < NH; j++) {
            float a = 0.f;
#pragma unroll
            for (int l = 0; l < LD; l++)
                a = fmaf(pq[i * LD + l], pk[j * LD + l], a);
            s[i * NH + j] = a;
        }

    __shared__ float sW[8][NH * NH];
    __shared__ float sA[NH * NH];

#pragma unroll
    for (int tt = 0; tt < NH * NH; tt++) {
        float x = s[tt];
#pragma unroll
        for (int off = 16; off > 0; off >>= 1)
            x += __shfl_down_sync(0xffffffffu, x, off);
        if (lane == 0) sW[wid][tt] = x;
    }
    __syncthreads();

    if (c < NH) {
        const int i = c;
        const float inv_scale = rsqrtf((float)(C_DIM * LD));
        float row[NH];
        float mx = -1e30f;
#pragma unroll
        for (int j = 0; j < NH; j++) {
            float a = 0.f;
#pragma unroll
            for (int w = 0; w < 8; w++) a += sW[w][i * NH + j];
            row[j] = a * inv_scale;
            mx = fmaxf(mx, row[j]);
        }
        float sum = 0.f;
#pragma unroll
        for (int j = 0; j < NH; j++) { row[j] = expf(row[j] - mx); sum += row[j]; }
        float inv = 1.f / sum;
#pragma unroll
        for (int j = 0; j < NH; j++) sA[i * NH + j] = row[j] * inv;
    }
    __syncthreads();

    const int row = b * C_DIM + c;
    const int R8i = row >> 3, gg = row & 7;
    unsigned* __restrict__ vp = (unsigned*)g_Vp;
#pragma unroll
    for (int n = 0; n < NH; n++)
#pragma unroll
        for (int l = 0; l < LD; l++) {
            float a = pv[n * LD + l];
#pragma unroll
            for (int j = 0; j < NH; j++)
                a = fmaf(sA[n * NH + j], pv[j * LD + l], a);
            const int kk = n * LD + l;
            const int K8 = kk >> 3, tt = kk & 3, hf = (kk >> 2) & 1;
            vp[((R8i * 7 + K8) * 32 + gg * 4 + tt) * 2 + hf] = f2tf32(a);
        }
    // zero-pad kk = 50..55
#pragma unroll
    for (int kk = PROJ; kk < 56; kk++) {
        const int K8 = kk >> 3, tt = kk & 3, hf = (kk >> 2) & 1;
        vp[((R8i * 7 + K8) * 32 + gg * 4 + tt) * 2 + hf] = 0u;
    }
}

// ---------------------------------------------------------------------------
// K3: output GEMM + residual + fused BN partial stats.
// out[8192,4096] = v + Va@wfc.  Fragments straight from packed globals:
// no smem mainloop, no fills, no pre-sync. 42 coalesced L2-hit LDGs/warp.
// Epilogue: stage acc -> Acc[128][68] smem, stream float4 + row stats.
// ---------------------------------------------------------------------------
__global__ __launch_bounds__(256) void k_out_tc(
    const float* __restrict__ v, float* __restrict__ out)
{
    __shared__ float Acc[128][68];

    const int tid  = threadIdx.x;
    const int warp = tid >> 5;
    const int lane = tid & 31;
    const int g = lane >> 2;
    const int t = lane & 3;
    const int wrow = (warp & 3) * 32;   // data rows (mma-N)
    const int wcol = (warp >> 2) * 32;  // out cols (mma-M)
    const int n0 = blockIdx.x * 64;
    const int m0 = blockIdx.y * 128;

    const uint4* __restrict__ Wp =
        g_Wp + (size_t)(blockIdx.x * 4 + (warp >> 2) * 2) * 7 * 32;
    const uint2* __restrict__ Vp =
        g_Vp + (size_t)((m0 >> 3) + (warp & 3) * 4) * 7 * 32;

    float acc[2][4][4];
#pragma unroll
    for (int mi = 0; mi < 2; mi++)
#pragma unroll
        for (int ni = 0; ni < 4; ni++)
#pragma unroll
            for (int r = 0; r < 4; r++) acc[mi][ni][r] = 0.f;

#pragma unroll
    for (int ks = 0; ks < 7; ks++) {
        uint4 av0 = __ldg(&Wp[ks * 32 + lane]);
        uint4 av1 = __ldg(&Wp[(7 + ks) * 32 + lane]);
#pragma unroll
        for (int ni = 0; ni < 4; ni++) {
            uint2 bv = __ldg(&Vp[(ni * 7 + ks) * 32 + lane]);
            mma_tf32(acc[0][ni], av0.x, av0.y, av0.z, av0.w, bv.x, bv.y);
            mma_tf32(acc[1][ni], av1.x, av1.y, av1.z, av1.w, bv.x, bv.y);
        }
    }

    // stage accumulators into smem
#pragma unroll
    for (int mi = 0; mi < 2; mi++) {
#pragma unroll
        for (int ni = 0; ni < 4; ni++) {
            int row = wrow + ni * 8 + 2 * t;
            int col = wcol + mi * 16 + g;
            Acc[row][col]         = acc[mi][ni][0];
            Acc[row + 1][col]     = acc[mi][ni][1];
            Acc[row][col + 8]     = acc[mi][ni][2];
            Acc[row + 1][col + 8] = acc[mi][ni][3];
        }
    }
    __syncthreads();

    // streamed epilogue: 8 x float4 per thread, full row per 16-lane group
#pragma unroll
    for (int it = 0; it < 8; it++) {
        int f   = tid + it * 256;
        int row = f >> 4;
        int c4  = (f & 15) * 4;
        float4 a = *(float4*)&Acc[row][c4];
        size_t gi = (size_t)(m0 + row) * HW + n0 + c4;
        float4 vv = *(const float4*)&v[gi];
        float4 o;
        o.x = vv.x + a.x;
        o.y = vv.y + a.y;
        o.z = vv.z + a.z;
        o.w = vv.w + a.w;
        *(float4*)&out[gi] = o;
        float s  = (o.x + o.y) + (o.z + o.w);
        float qq = (o.x * o.x + o.y * o.y) + (o.z * o.z + o.w * o.w);
#pragma unroll
        for (int msk = 1; msk <= 8; msk <<= 1) {
            s  += __shfl_xor_sync(0xffffffffu, s, msk);
            qq += __shfl_xor_sync(0xffffffffu, qq, msk);
        }
        if ((lane & 15) == 0) {
            g_osum[blockIdx.x][m0 + row] = s;
            g_osq[blockIdx.x][m0 + row]  = qq;
        }
    }
}

// ---------------------------------------------------------------------------
// K4: combine partials -> per-channel scale/shift. 256 blocks x 256 thr.
// ---------------------------------------------------------------------------
__global__ __launch_bounds__(256) void k_bnfinal(
    const float* __restrict__ gamma, const float* __restrict__ beta)
{
    const int c = blockIdx.x;
    const int tid = threadIdx.x;
    float s = 0.f, s2 = 0.f;
    for (int i = tid; i < B_DIM * 64; i += 256) {     // 2048 entries
        int b  = i >> 6;
        int nb = i & 63;
        int row = b * C_DIM + c;
        s  += g_osum[nb][row];
        s2 += g_osq[nb][row];
    }
    __shared__ float rs[256], rs2[256];
    rs[tid] = s; rs2[tid] = s2;
    __syncthreads();
    for (int off = 128; off > 0; off >>= 1) {
        if (tid < off) { rs[tid] += rs[tid + off]; rs2[tid] += rs2[tid + off]; }
        __syncthreads();
    }
    if (tid == 0) {
        const float inv_n = 1.f / (float)(B_DIM * HW);
        float mean = rs[0] * inv_n;
        float var  = rs2[0] * inv_n - mean * mean;
        float sc = gamma[c] * rsqrtf(var + BN_EPS);
        g_scale[c] = sc;
        g_shift[c] = beta[c] - mean * sc;
    }
}

// ---------------------------------------------------------------------------
// K5: apply BN affine in place.
// ---------------------------------------------------------------------------
__global__ __launch_bounds__(256) void k_apply(float* __restrict__ out)
{
    float4* __restrict__ p = (float4*)out;
    const int idx = blockIdx.x * 256 + threadIdx.x;
#pragma unroll
    for (int tt = 0; tt < 4; tt++) {
        int i = idx + tt * (8192 * 256);
        int c = (i >> 10) & 255;
        float sc = g_scale[c], sh = g_shift[c];
        float4 x = p[i];
        x.x = fmaf(x.x, sc, sh);
        x.y = fmaf(x.y, sc, sh);
        x.z = fmaf(x.z, sc, sh);
        x.w = fmaf(x.w, sc, sh);
        p[i] = x;
    }
}

// ---------------------------------------------------------------------------
extern "C" void kernel_launch(void* const* d_in, const int* in_sizes, int n_in,
                              void* d_out, int out_size)
{
    (void)in_sizes; (void)n_in; (void)out_size;
    const float* q     = (const float*)d_in[0];
    const float* k     = (const float*)d_in[1];
    const float* v     = (const float*)d_in[2];
    const float* wq    = (const float*)d_in[3];
    const float* wk    = (const float*)d_in[4];
    const float* wv    = (const float*)d_in[5];
    const float* wfc   = (const float*)d_in[6];
    const float* gamma = (const float*)d_in[7];
    const float* beta  = (const float*)d_in[8];
    float* out = (float*)d_out;

    k_proj_tc<<<dim3(M_ROWS / 128, KSPLIT, 3), 256>>>(q, k, v, wq, wk, wv);
    k_packW<<<(4096 * 56) / 256, 256>>>(wfc);
    k_reduceP<<<(3 * M_ROWS * PROJ / 4) / 256, 256>>>();
    k_attn<<<B_DIM, 256>>>();
    k_out_tc<<<dim3(HW / 64, M_ROWS / 128), 256>>>(v, out);
    k_bnfinal<<<C_DIM, 256>>>(gamma, beta);
    k_apply<<<8192, 256>>>(out);
}